// round 14
// baseline (speedup 1.0000x reference)
#include <cuda_runtime.h>

// Problem constants
#define Nn 1024   // nodes (== hidden_dim)
#define Tt 32     // seq len
#define Dd 256    // state dim
#define Hh 1024   // hidden dim
#define Ee 64     // action logits
#define DH (Dd + Hh)   // 1280
#define BK 8

// ---------------- scratch: __device__ globals, referenced ONLY from kernels
__device__ float g_WZR[DH * 2 * Hh];        // [Wz@adj | Wr@adj] (1280 x 2048)
__device__ float g_WC [DH * Hh];            // Wh@adj            (1280 x 1024)
__device__ float g_Bzr[Tt * Nn * 2 * Hh];   // x@Wx'+bias (gates), per t
__device__ float g_Bc [Tt * Nn * Hh];       // x@Wx'+bias (cand),  per t
__device__ float g_h  [Nn * Hh];            // hidden state
__device__ float g_z  [Nn * Hh];            // update gate
__device__ float g_rh [Nn * Hh];            // r * h

__device__ __forceinline__ float sigm(float x) { return 1.0f / (1.0f + expf(-x)); }

// ================= 256-thread GEMM core (fold / precompute; proven R13) ====
template <int BM, int BN>
__device__ __forceinline__ void mm_tile(const float (*Asb)[BM], const float (*Bsb)[BN],
                                        int trow, int tcol, float (*acc)[BN / 16])
{
    constexpr int TM = BM / 16, TN = BN / 16;
#pragma unroll
    for (int kk = 0; kk < BK; kk++) {
        float ra[TM], rb[TN];
#pragma unroll
        for (int i = 0; i < TM; i++) ra[i] = Asb[kk][trow + i];
#pragma unroll
        for (int j = 0; j < TN; j++) rb[j] = Bsb[kk][tcol + j];
#pragma unroll
        for (int i = 0; i < TM; i++)
#pragma unroll
            for (int j = 0; j < TN; j++) acc[i][j] += ra[i] * rb[j];
    }
}

template <int BM, int BN>
__device__ __forceinline__ void gemm_core(const float* __restrict__ A, int lda,
                                          const float* __restrict__ B, int ldb, int K,
                                          float (*acc)[BN / 16],
                                          float (*As)[BK][BM], float (*Bs)[BK][BN])
{
    const int tid  = threadIdx.x;
    const int trow = (tid >> 4) * (BM / 16);
    const int tcol = (tid & 15) * (BN / 16);
    const int aRow = tid >> 1;
    const int aCol = (tid & 1) * 4;
    const int bRow = tid / (BN / 4);
    const int bCol = (tid % (BN / 4)) * 4;
    const bool aAct = tid < 2 * BM;
    const bool bAct = tid < 2 * BN;

    float4 av, bv;
    if (aAct) {
        av = *(const float4*)(A + aRow * lda + aCol);
        As[0][aCol + 0][aRow] = av.x;  As[0][aCol + 1][aRow] = av.y;
        As[0][aCol + 2][aRow] = av.z;  As[0][aCol + 3][aRow] = av.w;
    }
    if (bAct) {
        bv = *(const float4*)(B + bRow * ldb + bCol);
        *(float4*)(&Bs[0][bRow][bCol]) = bv;
    }
    __syncthreads();

    int buf = 0;
    for (int k0 = BK; k0 < K; k0 += BK) {
        if (aAct) av = *(const float4*)(A + aRow * lda + k0 + aCol);
        if (bAct) bv = *(const float4*)(B + (k0 + bRow) * ldb + bCol);
        mm_tile<BM, BN>(As[buf], Bs[buf], trow, tcol, acc);
        if (aAct) {
            As[buf ^ 1][aCol + 0][aRow] = av.x;  As[buf ^ 1][aCol + 1][aRow] = av.y;
            As[buf ^ 1][aCol + 2][aRow] = av.z;  As[buf ^ 1][aCol + 3][aRow] = av.w;
        }
        if (bAct) *(float4*)(&Bs[buf ^ 1][bRow][bCol]) = bv;
        __syncthreads();
        buf ^= 1;
    }
    mm_tile<BM, BN>(As[buf], Bs[buf], trow, tcol, acc);
}

// ================= 512-thread GEMM core (serial loop; 4 warps/SMSP) ========
// Thread grid 32x16: TM rows x 8 cols per thread. BN fixed at 128.
// A loaders: tid < 2*BM (one float4 each). B loaders: tid in [256, 512).
template <int BM, int TM>
__device__ __forceinline__ void mm512(const float (*Asb)[BM], const float (*Bsb)[128],
                                      int trow, int tcol, float (*acc)[8])
{
#pragma unroll
    for (int kk = 0; kk < BK; kk++) {
        float ra[TM], rb[8];
#pragma unroll
        for (int i = 0; i < TM; i++) ra[i] = Asb[kk][trow + i];
#pragma unroll
        for (int j = 0; j < 8; j++) rb[j] = Bsb[kk][tcol + j];
#pragma unroll
        for (int i = 0; i < TM; i++)
#pragma unroll
            for (int j = 0; j < 8; j++) acc[i][j] += ra[i] * rb[j];
    }
}

template <int BM, int TM>
__device__ __forceinline__ void gemm512(const float* __restrict__ A, int lda,
                                        const float* __restrict__ B, int ldb, int K,
                                        float (*acc)[8],
                                        float (*As)[BK][BM], float (*Bs)[BK][128])
{
    const int tid  = threadIdx.x;
    const int trow = (tid >> 4) * TM;
    const int tcol = (tid & 15) * 8;
    const bool aAct = tid < 2 * BM;          // BM*BK/4 float4 loads
    const int aRow = tid >> 1;
    const int aCol = (tid & 1) * 4;
    const bool bAct = tid >= 256;            // 256 float4 loads (8x128)
    const int bTid = tid - 256;
    const int bRow = bTid >> 5;
    const int bCol = (bTid & 31) * 4;

    float4 av, bv;
    if (aAct) {
        av = *(const float4*)(A + aRow * lda + aCol);
        As[0][aCol + 0][aRow] = av.x;  As[0][aCol + 1][aRow] = av.y;
        As[0][aCol + 2][aRow] = av.z;  As[0][aCol + 3][aRow] = av.w;
    }
    if (bAct) {
        bv = *(const float4*)(B + bRow * ldb + bCol);
        *(float4*)(&Bs[0][bRow][bCol]) = bv;
    }
    __syncthreads();

    int buf = 0;
    for (int k0 = BK; k0 < K; k0 += BK) {
        if (aAct) av = *(const float4*)(A + aRow * lda + k0 + aCol);
        if (bAct) bv = *(const float4*)(B + (k0 + bRow) * ldb + bCol);
        mm512<BM, TM>(As[buf], Bs[buf], trow, tcol, acc);
        if (aAct) {
            As[buf ^ 1][aCol + 0][aRow] = av.x;  As[buf ^ 1][aCol + 1][aRow] = av.y;
            As[buf ^ 1][aCol + 2][aRow] = av.z;  As[buf ^ 1][aCol + 3][aRow] = av.w;
        }
        if (bAct) *(float4*)(&Bs[buf ^ 1][bRow][bCol]) = bv;
        __syncthreads();
        buf ^= 1;
    }
    mm512<BM, TM>(As[buf], Bs[buf], trow, tcol, acc);
}

// ---------------- fold: W' = W @ adj, all 3 gates in one launch (z-dim) ----
__global__ void __launch_bounds__(256)
fold_k(const float* __restrict__ Wz, const float* __restrict__ Wr,
       const float* __restrict__ Wh, const float* __restrict__ adj)
{
    __shared__ float As[2][BK][128];
    __shared__ float Bs[2][BK][128];
    float acc[8][8] = {};
    const int zz = blockIdx.z;
    const float* W = (zz == 0) ? Wz : (zz == 1) ? Wr : Wh;
    gemm_core<128, 128>(W + blockIdx.y * 128 * Hh, Hh,
                        adj + blockIdx.x * 128, Nn, Hh, acc, As, Bs);
    const int row0 = blockIdx.y * 128 + (threadIdx.x >> 4) * 8;
    const int col0 = blockIdx.x * 128 + (threadIdx.x & 15) * 8;
#pragma unroll
    for (int i = 0; i < 8; i++)
#pragma unroll
        for (int j = 0; j < 8; j++) {
            const float v = acc[i][j];
            if (zz == 0)      g_WZR[(row0 + i) * 2 * Hh + col0 + j]      = v;
            else if (zz == 1) g_WZR[(row0 + i) * 2 * Hh + Hh + col0 + j] = v;
            else              g_WC [(row0 + i) * Hh + col0 + j]          = v;
        }
}

// ---------------- precompute x-path for ALL t (time-parallel) --------------
template <int WHICH>
__global__ void __launch_bounds__(256)
pre_k(const float* __restrict__ x, const float* __restrict__ b0,
      const float* __restrict__ b1)
{
    __shared__ float As[2][BK][128];
    __shared__ float Bs[2][BK][128];
    float acc[8][8] = {};
    const float* B = ((WHICH == 0) ? &g_WZR[0] : &g_WC[0]) + blockIdx.x * 128;
    const int ldb = (WHICH == 0) ? 2 * Hh : Hh;
    gemm_core<128, 128>(x + blockIdx.y * 128 * Dd, Dd, B, ldb, Dd, acc, As, Bs);
    const int row0 = blockIdx.y * 128 + (threadIdx.x >> 4) * 8;
    const int col0 = blockIdx.x * 128 + (threadIdx.x & 15) * 8;
#pragma unroll
    for (int i = 0; i < 8; i++) {
        const int m = row0 + i, n = m >> 5, tt = m & 31;
#pragma unroll
        for (int j = 0; j < 8; j++) {
            const int col = col0 + j;
            if (WHICH == 0) {
                const float bias = (col < Hh) ? b0[col] : b1[col - Hh];
                g_Bzr[(tt * Nn + n) * 2 * Hh + col] = acc[i][j] + bias;
            } else {
                g_Bc[(tt * Nn + n) * Hh + col] = acc[i][j] + b0[col];
            }
        }
    }
}

// ---------------- fc + argmax body (softmax elided; OUTPUT IS FLOAT32) -----
// 512-thread block handles 8 nodes (64 threads/node, one logit per thread).
__device__ __forceinline__ void fc_body(int nodeBase,
                                        const float* __restrict__ fcw,
                                        const float* __restrict__ fcb,
                                        float* __restrict__ out, int t)
{
    const int tid = threadIdx.x;
    const int grp = tid >> 6;          // 0..7
    const int e   = tid & 63;          // logit index
    const int n   = nodeBase + grp;

    float acc = fcb[e];
    const float* hrow = &g_h[0] + n * Hh;
#pragma unroll 8
    for (int k = 0; k < Hh; k++) acc += hrow[k] * fcw[k * Ee + e];

    // warp-level argmax (each warp holds 32 logits of this node)
    float v = acc; int bi = e;
#pragma unroll
    for (int off = 16; off; off >>= 1) {
        float ov = __shfl_down_sync(0xffffffffu, v, off);
        int   oi = __shfl_down_sync(0xffffffffu, bi, off);
        if (ov > v || (ov == v && oi < bi)) { v = ov; bi = oi; }
    }
    __shared__ float wv[16];
    __shared__ int   wi[16];
    const int wid = tid >> 5;          // 0..15 (2 warps per node)
    if ((tid & 31) == 0) { wv[wid] = v; wi[wid] = bi; }
    __syncthreads();
    if (e == 0) {
        const int w0 = grp * 2, w1 = w0 + 1;
        int r = wi[w0];
        if (wv[w1] > wv[w0] || (wv[w1] == wv[w0] && wi[w1] < wi[w0])) r = wi[w1];
        out[n * Tt + t] = (float)r;    // (N, T, 1), float32 value
    }
}

// ---------------- fused serial gates + fc(t-1) -----------------------------
// blocks [0,128): gates GEMM [z|r] = h @ WZR[256:,:]  (h is h(t-1))
// blocks [128,256): fc+argmax for t-1 (also reads h(t-1) only)
__global__ void __launch_bounds__(512)
gatesfc_k(int t, const float* __restrict__ fcw, const float* __restrict__ fcb,
          float* __restrict__ out)
{
    __shared__ float As[2][BK][128];
    __shared__ float Bs[2][BK][128];
    const int bid = blockIdx.x;
    if (bid < 128) {
        const int bx = bid & 15, by = bid >> 4;
        float acc[4][8] = {};
        gemm512<128, 4>(&g_h[0] + by * 128 * Hh, Hh,
                        &g_WZR[0] + Dd * 2 * Hh + bx * 128, 2 * Hh,
                        Hh, acc, As, Bs);
        const int row0 = by * 128 + (threadIdx.x >> 4) * 4;
        const int col0 = bx * 128 + (threadIdx.x & 15) * 8;
        const float* P = &g_Bzr[0] + t * Nn * 2 * Hh;
        const bool zside = bx < 8;
#pragma unroll
        for (int i = 0; i < 4; i++) {
            const int row = row0 + i;
#pragma unroll
            for (int j = 0; j < 8; j++) {
                const int col = col0 + j;
                const float v = acc[i][j] + P[row * 2 * Hh + col];
                if (zside) {
                    g_z[row * Hh + col] = sigm(v);
                } else {
                    const int c = col - Hh;
                    g_rh[row * Hh + c] = g_h[row * Hh + c] * sigm(v);
                }
            }
        }
    } else {
        fc_body((bid - 128) * 8, fcw, fcb, out, t - 1);
    }
}

// ---------------- serial candidate + GRU update (64x128, 512 threads) ------
__global__ void __launch_bounds__(512)
cand_k(int t)
{
    __shared__ float As[2][BK][64];
    __shared__ float Bs[2][BK][128];
    float acc[2][8] = {};
    gemm512<64, 2>(&g_rh[0] + blockIdx.y * 64 * Hh, Hh,
                   &g_WC[0] + Dd * Hh + blockIdx.x * 128, Hh,
                   Hh, acc, As, Bs);
    const int row0 = blockIdx.y * 64 + (threadIdx.x >> 4) * 2;
    const int col0 = blockIdx.x * 128 + (threadIdx.x & 15) * 8;
    const float* P = &g_Bc[0] + t * Nn * Hh;
#pragma unroll
    for (int i = 0; i < 2; i++) {
#pragma unroll
        for (int j = 0; j < 8; j++) {
            const int idx = (row0 + i) * Hh + col0 + j;
            const float ht = tanhf(acc[i][j] + P[idx]);
            const float z  = g_z[idx];
            const float h  = g_h[idx];
            g_h[idx] = sigm(z * h + (1.0f - z) * ht);
        }
    }
}

// ---------------- standalone fc (final step) -------------------------------
__global__ void __launch_bounds__(512)
fc_k(const float* __restrict__ fcw, const float* __restrict__ fcb,
     float* __restrict__ out, int t)
{
    fc_body(blockIdx.x * 8, fcw, fcb, out, t);
}

// ---------------- t=0 degenerate step (h0 = 0 => GEMMs vanish) -------------
__global__ void __launch_bounds__(256)
step0_k()
{
    const int idx = blockIdx.x * blockDim.x + threadIdx.x;  // [0, N*H)
    const int n = idx >> 10, c = idx & 1023;
    const float z  = sigm(g_Bzr[n * 2 * Hh + c]);           // t=0, z half
    const float ht = tanhf(g_Bc[idx]);                      // t=0
    g_h[idx] = sigm((1.0f - z) * ht);
}

// ---------------- launch --------------------------------------------------
extern "C" void kernel_launch(void* const* d_in, const int* in_sizes, int n_in,
                              void* d_out, int out_size)
{
    float* out = (float*)d_out;

    // Identify inputs by element count; fall back to positional order.
    const float *x = 0, *adj = 0, *Wz = 0, *Wr = 0, *Wh = 0;
    const float *bz = 0, *br = 0, *bh = 0, *fcw = 0, *fcb = 0;
    for (int i = 0; i < n_in; i++) {
        const int s = in_sizes[i];
        const float* p = (const float*)d_in[i];
        if      (s == Nn * Tt * Dd) x = p;
        else if (s == Nn * Nn)      adj = p;
        else if (s == DH * Hh)      { if (!Wz) Wz = p; else if (!Wr) Wr = p; else Wh = p; }
        else if (s == Hh)           { if (!bz) bz = p; else if (!br) br = p; else bh = p; }
        else if (s == Hh * Ee)      fcw = p;
        else if (s == Ee)           fcb = p;
    }
    if ((!x || !adj || !Wz || !Wr || !Wh || !bz || !br || !bh || !fcw || !fcb)
        && n_in >= 10) {
        x   = (const float*)d_in[0];
        adj = (const float*)d_in[1];
        Wz  = (const float*)d_in[2];  bz = (const float*)d_in[3];
        Wr  = (const float*)d_in[4];  br = (const float*)d_in[5];
        Wh  = (const float*)d_in[6];  bh = (const float*)d_in[7];
        fcw = (const float*)d_in[8];  fcb = (const float*)d_in[9];
    }

    // ---- fold all three W@adj in one launch (240 CTAs)
    fold_k<<<dim3(8, 10, 3), 256>>>(Wz, Wr, Wh, adj);

    // ---- time-parallel x-path precompute (full machine)
    pre_k<0><<<dim3(16, 256), 256>>>(x, bz, br);
    pre_k<1><<<dim3(8, 256), 256>>>(x, bh, 0);

    // ---- t = 0 (h0 = 0: GEMMs degenerate to elementwise)
    step0_k<<<(Nn * Hh) / 256, 256>>>();

    // ---- recurrent loop: gates(t) + fc(t-1) fused, then cand(t)
    for (int t = 1; t < Tt; t++) {
        gatesfc_k<<<256, 512>>>(t, fcw, fcb, out);   // 128 gates + 128 fc blocks
        cand_k<<<dim3(8, 16), 512>>>(t);             // h update (128 CTAs)
    }
    fc_k<<<128, 512>>>(fcw, fcb, out, Tt - 1);       // final argmax
}

// round 15
// speedup vs baseline: 1.1201x; 1.1201x over previous
#include <cuda_runtime.h>

// Problem constants
#define Nn 1024   // nodes (== hidden_dim)
#define Tt 32     // seq len
#define Dd 256    // state dim
#define Hh 1024   // hidden dim
#define Ee 64     // action logits
#define DH (Dd + Hh)   // 1280
#define BK 8

// ---------------- scratch: __device__ globals, referenced ONLY from kernels
__device__ float g_WZR[DH * 2 * Hh];        // [Wz@adj | Wr@adj] (1280 x 2048)
__device__ float g_WC [DH * Hh];            // Wh@adj            (1280 x 1024)
__device__ float g_Bzr[Tt * Nn * 2 * Hh];   // x@Wx'+bias (gates), per t
__device__ float g_Bc [Tt * Nn * Hh];       // x@Wx'+bias (cand),  per t
__device__ float g_h  [Nn * Hh];            // hidden state
__device__ float g_z  [Nn * Hh];            // update gate
__device__ float g_rh [Nn * Hh];            // r * h

__device__ __forceinline__ float sigm(float x) { return 1.0f / (1.0f + expf(-x)); }

// ================= 256-thread GEMM core (R13-proven; 8x8 register tile) ====
template <int BM, int BN>
__device__ __forceinline__ void mm_tile(const float (*Asb)[BM], const float (*Bsb)[BN],
                                        int trow, int tcol, float (*acc)[BN / 16])
{
    constexpr int TM = BM / 16, TN = BN / 16;
#pragma unroll
    for (int kk = 0; kk < BK; kk++) {
        float ra[TM], rb[TN];
#pragma unroll
        for (int i = 0; i < TM; i++) ra[i] = Asb[kk][trow + i];
#pragma unroll
        for (int j = 0; j < TN; j++) rb[j] = Bsb[kk][tcol + j];
#pragma unroll
        for (int i = 0; i < TM; i++)
#pragma unroll
            for (int j = 0; j < TN; j++) acc[i][j] += ra[i] * rb[j];
    }
}

template <int BM, int BN>
__device__ __forceinline__ void gemm_core(const float* __restrict__ A, int lda,
                                          const float* __restrict__ B, int ldb, int K,
                                          float (*acc)[BN / 16],
                                          float (*As)[BK][BM], float (*Bs)[BK][BN])
{
    const int tid  = threadIdx.x;
    const int trow = (tid >> 4) * (BM / 16);
    const int tcol = (tid & 15) * (BN / 16);
    const int aRow = tid >> 1;
    const int aCol = (tid & 1) * 4;
    const int bRow = tid / (BN / 4);
    const int bCol = (tid % (BN / 4)) * 4;
    const bool aAct = tid < 2 * BM;
    const bool bAct = tid < 2 * BN;

    float4 av, bv;
    if (aAct) {
        av = *(const float4*)(A + aRow * lda + aCol);
        As[0][aCol + 0][aRow] = av.x;  As[0][aCol + 1][aRow] = av.y;
        As[0][aCol + 2][aRow] = av.z;  As[0][aCol + 3][aRow] = av.w;
    }
    if (bAct) {
        bv = *(const float4*)(B + bRow * ldb + bCol);
        *(float4*)(&Bs[0][bRow][bCol]) = bv;
    }
    __syncthreads();

    int buf = 0;
    for (int k0 = BK; k0 < K; k0 += BK) {
        if (aAct) av = *(const float4*)(A + aRow * lda + k0 + aCol);
        if (bAct) bv = *(const float4*)(B + (k0 + bRow) * ldb + bCol);
        mm_tile<BM, BN>(As[buf], Bs[buf], trow, tcol, acc);
        if (aAct) {
            As[buf ^ 1][aCol + 0][aRow] = av.x;  As[buf ^ 1][aCol + 1][aRow] = av.y;
            As[buf ^ 1][aCol + 2][aRow] = av.z;  As[buf ^ 1][aCol + 3][aRow] = av.w;
        }
        if (bAct) *(float4*)(&Bs[buf ^ 1][bRow][bCol]) = bv;
        __syncthreads();
        buf ^= 1;
    }
    mm_tile<BM, BN>(As[buf], Bs[buf], trow, tcol, acc);
}

// ---------------- fold: W' = W @ adj, all 3 gates in one launch (z-dim) ----
__global__ void __launch_bounds__(256)
fold_k(const float* __restrict__ Wz, const float* __restrict__ Wr,
       const float* __restrict__ Wh, const float* __restrict__ adj)
{
    __shared__ float As[2][BK][128];
    __shared__ float Bs[2][BK][128];
    float acc[8][8] = {};
    const int zz = blockIdx.z;
    const float* W = (zz == 0) ? Wz : (zz == 1) ? Wr : Wh;
    gemm_core<128, 128>(W + blockIdx.y * 128 * Hh, Hh,
                        adj + blockIdx.x * 128, Nn, Hh, acc, As, Bs);
    const int row0 = blockIdx.y * 128 + (threadIdx.x >> 4) * 8;
    const int col0 = blockIdx.x * 128 + (threadIdx.x & 15) * 8;
#pragma unroll
    for (int i = 0; i < 8; i++)
#pragma unroll
        for (int j = 0; j < 8; j++) {
            const float v = acc[i][j];
            if (zz == 0)      g_WZR[(row0 + i) * 2 * Hh + col0 + j]      = v;
            else if (zz == 1) g_WZR[(row0 + i) * 2 * Hh + Hh + col0 + j] = v;
            else              g_WC [(row0 + i) * Hh + col0 + j]          = v;
        }
}

// ---------------- precompute x-path for ALL t (time-parallel) --------------
template <int WHICH>
__global__ void __launch_bounds__(256)
pre_k(const float* __restrict__ x, const float* __restrict__ b0,
      const float* __restrict__ b1)
{
    __shared__ float As[2][BK][128];
    __shared__ float Bs[2][BK][128];
    float acc[8][8] = {};
    const float* B = ((WHICH == 0) ? &g_WZR[0] : &g_WC[0]) + blockIdx.x * 128;
    const int ldb = (WHICH == 0) ? 2 * Hh : Hh;
    gemm_core<128, 128>(x + blockIdx.y * 128 * Dd, Dd, B, ldb, Dd, acc, As, Bs);
    const int row0 = blockIdx.y * 128 + (threadIdx.x >> 4) * 8;
    const int col0 = blockIdx.x * 128 + (threadIdx.x & 15) * 8;
#pragma unroll
    for (int i = 0; i < 8; i++) {
        const int m = row0 + i, n = m >> 5, tt = m & 31;
#pragma unroll
        for (int j = 0; j < 8; j++) {
            const int col = col0 + j;
            if (WHICH == 0) {
                const float bias = (col < Hh) ? b0[col] : b1[col - Hh];
                g_Bzr[(tt * Nn + n) * 2 * Hh + col] = acc[i][j] + bias;
            } else {
                g_Bc[(tt * Nn + n) * Hh + col] = acc[i][j] + b0[col];
            }
        }
    }
}

// ---------------- fc + argmax body (256 threads: 4 nodes x 64 logits) ------
__device__ __forceinline__ void fc_body(int nodeBase,
                                        const float* __restrict__ fcw,
                                        const float* __restrict__ fcb,
                                        float* __restrict__ out, int t)
{
    const int tid = threadIdx.x;
    const int grp = tid >> 6;          // 0..3
    const int e   = tid & 63;          // logit index
    const int n   = nodeBase + grp;

    float acc = fcb[e];
    const float* hrow = &g_h[0] + n * Hh;
#pragma unroll 8
    for (int k = 0; k < Hh; k++) acc += hrow[k] * fcw[k * Ee + e];

    // warp-level argmax; warp w covers e = (w&1)*32 + lane of node grp
    float v = acc; int bi = e;
#pragma unroll
    for (int off = 16; off; off >>= 1) {
        float ov = __shfl_down_sync(0xffffffffu, v, off);
        int   oi = __shfl_down_sync(0xffffffffu, bi, off);
        if (ov > v || (ov == v && oi < bi)) { v = ov; bi = oi; }
    }
    __shared__ float wv[8];
    __shared__ int   wi[8];
    const int wid = tid >> 5;          // 0..7 (2 warps per node)
    if ((tid & 31) == 0) { wv[wid] = v; wi[wid] = bi; }
    __syncthreads();
    if (e == 0) {
        const int w0 = grp * 2, w1 = w0 + 1;
        int r = wi[w0];
        if (wv[w1] > wv[w0] || (wv[w1] == wv[w0] && wi[w1] < wi[w0])) r = wi[w1];
        out[n * Tt + t] = (float)r;    // (N, T, 1), float32 value
    }
}

// ---------------- fused serial gates(t) + fc(t-1) --------------------------
// blocks [0,128): gates GEMM [z|r] = h @ WZR[256:,:] (reads h(t-1))
// blocks [128,384): fc+argmax for t-1 (also reads h(t-1) only) — fills the
// ~20 SMs the 128 gates CTAs leave idle.
__global__ void __launch_bounds__(256)
gatesfc_k(int t, const float* __restrict__ fcw, const float* __restrict__ fcb,
          float* __restrict__ out)
{
    __shared__ float As[2][BK][128];
    __shared__ float Bs[2][BK][128];
    const int bid = blockIdx.x;
    if (bid < 128) {
        const int bx = bid & 15, by = bid >> 4;
        float acc[8][8] = {};
        gemm_core<128, 128>(&g_h[0] + by * 128 * Hh, Hh,
                            &g_WZR[0] + Dd * 2 * Hh + bx * 128, 2 * Hh,
                            Hh, acc, As, Bs);
        const int row0 = by * 128 + (threadIdx.x >> 4) * 8;
        const int col0 = bx * 128 + (threadIdx.x & 15) * 8;
        const float* P = &g_Bzr[0] + t * Nn * 2 * Hh;
        const bool zside = bx < 8;
#pragma unroll
        for (int i = 0; i < 8; i++) {
            const int row = row0 + i;
#pragma unroll
            for (int j = 0; j < 8; j++) {
                const int col = col0 + j;
                const float v = acc[i][j] + P[row * 2 * Hh + col];
                if (zside) {
                    g_z[row * Hh + col] = sigm(v);
                } else {
                    const int c = col - Hh;
                    g_rh[row * Hh + c] = g_h[row * Hh + c] * sigm(v);
                }
            }
        }
    } else {
        fc_body((bid - 128) * 4, fcw, fcb, out, t - 1);
    }
}

// ---------------- serial candidate + GRU update (R13-proven 64x128) --------
__global__ void __launch_bounds__(256)
cand_k(int t)
{
    __shared__ float As[2][BK][64];
    __shared__ float Bs[2][BK][128];
    float acc[4][8] = {};
    gemm_core<64, 128>(&g_rh[0] + blockIdx.y * 64 * Hh, Hh,
                       &g_WC[0] + Dd * Hh + blockIdx.x * 128, Hh,
                       Hh, acc, As, Bs);
    const int row0 = blockIdx.y * 64 + (threadIdx.x >> 4) * 4;
    const int col0 = blockIdx.x * 128 + (threadIdx.x & 15) * 8;
    const float* P = &g_Bc[0] + t * Nn * Hh;
#pragma unroll
    for (int i = 0; i < 4; i++) {
#pragma unroll
        for (int j = 0; j < 8; j++) {
            const int idx = (row0 + i) * Hh + col0 + j;
            const float ht = tanhf(acc[i][j] + P[idx]);
            const float z  = g_z[idx];
            const float h  = g_h[idx];
            g_h[idx] = sigm(z * h + (1.0f - z) * ht);
        }
    }
}

// ---------------- standalone fc (final step) -------------------------------
__global__ void __launch_bounds__(256)
fc_k(const float* __restrict__ fcw, const float* __restrict__ fcb,
     float* __restrict__ out, int t)
{
    fc_body(blockIdx.x * 4, fcw, fcb, out, t);
}

// ---------------- t=0 degenerate step (h0 = 0 => GEMMs vanish) -------------
__global__ void __launch_bounds__(256)
step0_k()
{
    const int idx = blockIdx.x * blockDim.x + threadIdx.x;  // [0, N*H)
    const int n = idx >> 10, c = idx & 1023;
    const float z  = sigm(g_Bzr[n * 2 * Hh + c]);           // t=0, z half
    const float ht = tanhf(g_Bc[idx]);                      // t=0
    g_h[idx] = sigm((1.0f - z) * ht);
}

// ---------------- launch --------------------------------------------------
extern "C" void kernel_launch(void* const* d_in, const int* in_sizes, int n_in,
                              void* d_out, int out_size)
{
    float* out = (float*)d_out;

    // Identify inputs by element count; fall back to positional order.
    const float *x = 0, *adj = 0, *Wz = 0, *Wr = 0, *Wh = 0;
    const float *bz = 0, *br = 0, *bh = 0, *fcw = 0, *fcb = 0;
    for (int i = 0; i < n_in; i++) {
        const int s = in_sizes[i];
        const float* p = (const float*)d_in[i];
        if      (s == Nn * Tt * Dd) x = p;
        else if (s == Nn * Nn)      adj = p;
        else if (s == DH * Hh)      { if (!Wz) Wz = p; else if (!Wr) Wr = p; else Wh = p; }
        else if (s == Hh)           { if (!bz) bz = p; else if (!br) br = p; else bh = p; }
        else if (s == Hh * Ee)      fcw = p;
        else if (s == Ee)           fcb = p;
    }
    if ((!x || !adj || !Wz || !Wr || !Wh || !bz || !br || !bh || !fcw || !fcb)
        && n_in >= 10) {
        x   = (const float*)d_in[0];
        adj = (const float*)d_in[1];
        Wz  = (const float*)d_in[2];  bz = (const float*)d_in[3];
        Wr  = (const float*)d_in[4];  br = (const float*)d_in[5];
        Wh  = (const float*)d_in[6];  bh = (const float*)d_in[7];
        fcw = (const float*)d_in[8];  fcb = (const float*)d_in[9];
    }

    // ---- fold all three W@adj in one launch (240 CTAs)
    fold_k<<<dim3(8, 10, 3), 256>>>(Wz, Wr, Wh, adj);

    // ---- time-parallel x-path precompute (full machine)
    pre_k<0><<<dim3(16, 256), 256>>>(x, bz, br);
    pre_k<1><<<dim3(8, 256), 256>>>(x, bh, 0);

    // ---- t = 0 (h0 = 0: GEMMs degenerate to elementwise)
    step0_k<<<(Nn * Hh) / 256, 256>>>();

    // ---- recurrent loop: gates(t) + fc(t-1) fused, then cand(t)
    for (int t = 1; t < Tt; t++) {
        gatesfc_k<<<384, 256>>>(t, fcw, fcb, out);   // 128 gates + 256 fc blocks
        cand_k<<<dim3(8, 16), 256>>>(t);             // h update (128 CTAs)
    }
    fc_k<<<256, 256>>>(fcw, fcb, out, Tt - 1);       // final argmax
}

// round 17
// speedup vs baseline: 1.3237x; 1.1817x over previous
#include <cuda_runtime.h>

// Problem constants
#define Nn 1024   // nodes (== hidden_dim)
#define Tt 32     // seq len
#define Dd 256    // state dim
#define Hh 1024   // hidden dim
#define Ee 64     // action logits
#define DH (Dd + Hh)   // 1280
#define BK 8

// ---------------- scratch: __device__ globals, referenced ONLY from kernels
__device__ float g_WZR[DH * 2 * Hh];        // [Wz@adj | Wr@adj] (1280 x 2048)
__device__ float g_WC [DH * Hh];            // Wh@adj            (1280 x 1024)
__device__ float g_Bzr[Tt * Nn * 2 * Hh];   // x@Wx'+bias (gates), per t
__device__ float g_Bc [Tt * Nn * Hh];       // x@Wx'+bias (cand),  per t
__device__ float g_h  [Nn * Hh];            // hidden state
__device__ float g_z  [Nn * Hh];            // update gate
__device__ float g_rh [Nn * Hh];            // r * h

__device__ __forceinline__ float sigm(float x) { return 1.0f / (1.0f + expf(-x)); }

// ================= 256-thread GEMM core (R13-proven; 8x8 register tile) ====
template <int BM, int BN>
__device__ __forceinline__ void mm_tile(const float (*Asb)[BM], const float (*Bsb)[BN],
                                        int trow, int tcol, float (*acc)[BN / 16])
{
    constexpr int TM = BM / 16, TN = BN / 16;
#pragma unroll
    for (int kk = 0; kk < BK; kk++) {
        float ra[TM], rb[TN];
#pragma unroll
        for (int i = 0; i < TM; i++) ra[i] = Asb[kk][trow + i];
#pragma unroll
        for (int j = 0; j < TN; j++) rb[j] = Bsb[kk][tcol + j];
#pragma unroll
        for (int i = 0; i < TM; i++)
#pragma unroll
            for (int j = 0; j < TN; j++) acc[i][j] += ra[i] * rb[j];
    }
}

template <int BM, int BN>
__device__ __forceinline__ void gemm_core(const float* __restrict__ A, int lda,
                                          const float* __restrict__ B, int ldb, int K,
                                          float (*acc)[BN / 16],
                                          float (*As)[BK][BM], float (*Bs)[BK][BN])
{
    const int tid  = threadIdx.x;
    const int trow = (tid >> 4) * (BM / 16);
    const int tcol = (tid & 15) * (BN / 16);
    const int aRow = tid >> 1;
    const int aCol = (tid & 1) * 4;
    const int bRow = tid / (BN / 4);
    const int bCol = (tid % (BN / 4)) * 4;
    const bool aAct = tid < 2 * BM;
    const bool bAct = tid < 2 * BN;

    float4 av, bv;
    if (aAct) {
        av = *(const float4*)(A + aRow * lda + aCol);
        As[0][aCol + 0][aRow] = av.x;  As[0][aCol + 1][aRow] = av.y;
        As[0][aCol + 2][aRow] = av.z;  As[0][aCol + 3][aRow] = av.w;
    }
    if (bAct) {
        bv = *(const float4*)(B + bRow * ldb + bCol);
        *(float4*)(&Bs[0][bRow][bCol]) = bv;
    }
    __syncthreads();

    int buf = 0;
    for (int k0 = BK; k0 < K; k0 += BK) {
        if (aAct) av = *(const float4*)(A + aRow * lda + k0 + aCol);
        if (bAct) bv = *(const float4*)(B + (k0 + bRow) * ldb + bCol);
        mm_tile<BM, BN>(As[buf], Bs[buf], trow, tcol, acc);
        if (aAct) {
            As[buf ^ 1][aCol + 0][aRow] = av.x;  As[buf ^ 1][aCol + 1][aRow] = av.y;
            As[buf ^ 1][aCol + 2][aRow] = av.z;  As[buf ^ 1][aCol + 3][aRow] = av.w;
        }
        if (bAct) *(float4*)(&Bs[buf ^ 1][bRow][bCol]) = bv;
        __syncthreads();
        buf ^= 1;
    }
    mm_tile<BM, BN>(As[buf], Bs[buf], trow, tcol, acc);
}

// ---------------- fold: W' = W @ adj, all 3 gates in one launch (z-dim) ----
__global__ void __launch_bounds__(256)
fold_k(const float* __restrict__ Wz, const float* __restrict__ Wr,
       const float* __restrict__ Wh, const float* __restrict__ adj)
{
    __shared__ float As[2][BK][128];
    __shared__ float Bs[2][BK][128];
    float acc[8][8] = {};
    const int zz = blockIdx.z;
    const float* W = (zz == 0) ? Wz : (zz == 1) ? Wr : Wh;
    gemm_core<128, 128>(W + blockIdx.y * 128 * Hh, Hh,
                        adj + blockIdx.x * 128, Nn, Hh, acc, As, Bs);
    const int row0 = blockIdx.y * 128 + (threadIdx.x >> 4) * 8;
    const int col0 = blockIdx.x * 128 + (threadIdx.x & 15) * 8;
#pragma unroll
    for (int i = 0; i < 8; i++)
#pragma unroll
        for (int j = 0; j < 8; j++) {
            const float v = acc[i][j];
            if (zz == 0)      g_WZR[(row0 + i) * 2 * Hh + col0 + j]      = v;
            else if (zz == 1) g_WZR[(row0 + i) * 2 * Hh + Hh + col0 + j] = v;
            else              g_WC [(row0 + i) * Hh + col0 + j]          = v;
        }
}

// ---------------- precompute x-path for ALL t (time-parallel) --------------
template <int WHICH>
__global__ void __launch_bounds__(256)
pre_k(const float* __restrict__ x, const float* __restrict__ b0,
      const float* __restrict__ b1)
{
    __shared__ float As[2][BK][128];
    __shared__ float Bs[2][BK][128];
    float acc[8][8] = {};
    const float* B = ((WHICH == 0) ? &g_WZR[0] : &g_WC[0]) + blockIdx.x * 128;
    const int ldb = (WHICH == 0) ? 2 * Hh : Hh;
    gemm_core<128, 128>(x + blockIdx.y * 128 * Dd, Dd, B, ldb, Dd, acc, As, Bs);
    const int row0 = blockIdx.y * 128 + (threadIdx.x >> 4) * 8;
    const int col0 = blockIdx.x * 128 + (threadIdx.x & 15) * 8;
#pragma unroll
    for (int i = 0; i < 8; i++) {
        const int m = row0 + i, n = m >> 5, tt = m & 31;
#pragma unroll
        for (int j = 0; j < 8; j++) {
            const int col = col0 + j;
            if (WHICH == 0) {
                const float bias = (col < Hh) ? b0[col] : b1[col - Hh];
                g_Bzr[(tt * Nn + n) * 2 * Hh + col] = acc[i][j] + bias;
            } else {
                g_Bc[(tt * Nn + n) * Hh + col] = acc[i][j] + b0[col];
            }
        }
    }
}

// ---------------- serial gates: [z|r] = h @ WZR[256:,:], K=1024 (R13) ------
__global__ void __launch_bounds__(256)
gates_k(int t)
{
    __shared__ float As[2][BK][128];
    __shared__ float Bs[2][BK][128];
    float acc[8][8] = {};
    gemm_core<128, 128>(&g_h[0] + blockIdx.y * 128 * Hh, Hh,
                        &g_WZR[0] + Dd * 2 * Hh + blockIdx.x * 128, 2 * Hh,
                        Hh, acc, As, Bs);
    const int row0 = blockIdx.y * 128 + (threadIdx.x >> 4) * 8;
    const int col0 = blockIdx.x * 128 + (threadIdx.x & 15) * 8;
    const float* P = &g_Bzr[0] + t * Nn * 2 * Hh;
    const bool zside = (blockIdx.x * 128) < Hh;
#pragma unroll
    for (int i = 0; i < 8; i++) {
        const int row = row0 + i;
#pragma unroll
        for (int j = 0; j < 8; j++) {
            const int col = col0 + j;
            const float v = acc[i][j] + P[row * 2 * Hh + col];
            if (zside) {
                g_z[row * Hh + col] = sigm(v);
            } else {
                const int c = col - Hh;
                g_rh[row * Hh + c] = g_h[row * Hh + c] * sigm(v);
            }
        }
    }
}

// ---------------- serial candidate + GRU update (R13-proven 64x128) --------
__global__ void __launch_bounds__(256)
cand_k(int t)
{
    __shared__ float As[2][BK][64];
    __shared__ float Bs[2][BK][128];
    float acc[4][8] = {};
    gemm_core<64, 128>(&g_rh[0] + blockIdx.y * 64 * Hh, Hh,
                       &g_WC[0] + Dd * Hh + blockIdx.x * 128, Hh,
                       Hh, acc, As, Bs);
    const int row0 = blockIdx.y * 64 + (threadIdx.x >> 4) * 4;
    const int col0 = blockIdx.x * 128 + (threadIdx.x & 15) * 8;
    const float* P = &g_Bc[0] + t * Nn * Hh;
#pragma unroll
    for (int i = 0; i < 4; i++) {
#pragma unroll
        for (int j = 0; j < 8; j++) {
            const int idx = (row0 + i) * Hh + col0 + j;
            const float ht = tanhf(acc[i][j] + P[idx]);
            const float z  = g_z[idx];
            const float h  = g_h[idx];
            g_h[idx] = sigm(z * h + (1.0f - z) * ht);
        }
    }
}

// ---------------- fc + argmax, GEMM-style (smem-staged fcw) ----------------
// 128 blocks x 8 nodes. One warp per node; lane owns 2 logits (e = 2*lane,
// 2*lane+1). fcw tiles staged via smem: 32 MB total L2 traffic per step
// (vs 256 MB for the per-node streaming design). Warp-shfl argmax,
// first-max tie-breaking (lower lane = lower logit index).
__global__ void __launch_bounds__(256)
fc_k(const float* __restrict__ fcw, const float* __restrict__ fcb,
     float* __restrict__ out, int t)
{
    __shared__ float sh_h[8][32];     // 8 nodes x 32 K-slice
    __shared__ float sh_w[32][64];    // 32 K x 64 logits
    const int tid  = threadIdx.x;
    const int n    = tid >> 5;        // local node 0..7 (= warp id)
    const int lane = tid & 31;
    const int e0   = lane * 2;
    const int nodeBase = blockIdx.x * 8;

    float a0 = 0.f, a1 = 0.f;
    for (int k0 = 0; k0 < Hh; k0 += 32) {
        if (tid < 64) {               // h tile: 8 rows x 32 cols = 64 float4
            const int r = tid >> 3, c = (tid & 7) * 4;
            *(float4*)&sh_h[r][c] =
                *(const float4*)(&g_h[0] + (nodeBase + r) * Hh + k0 + c);
        }
        {                             // w tile: rows k0..k0+31 contiguous in fcw
            const float4* src = (const float4*)(fcw + k0 * Ee);
            float4* dst = (float4*)&sh_w[0][0];
            dst[tid] = src[tid];      // 512 float4 total, 2 per thread
            dst[tid + 256] = src[tid + 256];
        }
        __syncthreads();
#pragma unroll
        for (int kk = 0; kk < 32; kk++) {
            const float hv = sh_h[n][kk];
            const float2 wv = *(const float2*)&sh_w[kk][e0];
            a0 += hv * wv.x;
            a1 += hv * wv.y;
        }
        __syncthreads();
    }

    a0 += fcb[e0];
    a1 += fcb[e0 + 1];

    // local argmax over the 2 owned logits (strict > keeps lower index)
    float best = a0; int bi = e0;
    if (a1 > best) { best = a1; bi = e0 + 1; }
    // warp argmax (one warp == one node)
#pragma unroll
    for (int off = 16; off; off >>= 1) {
        const float ov = __shfl_down_sync(0xffffffffu, best, off);
        const int   oi = __shfl_down_sync(0xffffffffu, bi, off);
        if (ov > best || (ov == best && oi < bi)) { best = ov; bi = oi; }
    }
    if (lane == 0) out[(nodeBase + n) * Tt + t] = (float)bi;  // float32 output
}

// ---------------- t=0 degenerate step (h0 = 0 => GEMMs vanish) -------------
__global__ void __launch_bounds__(256)
step0_k()
{
    const int idx = blockIdx.x * blockDim.x + threadIdx.x;  // [0, N*H)
    const int n = idx >> 10, c = idx & 1023;
    const float z  = sigm(g_Bzr[n * 2 * Hh + c]);           // t=0, z half
    const float ht = tanhf(g_Bc[idx]);                      // t=0
    g_h[idx] = sigm((1.0f - z) * ht);
}

// ---------------- launch --------------------------------------------------
extern "C" void kernel_launch(void* const* d_in, const int* in_sizes, int n_in,
                              void* d_out, int out_size)
{
    float* out = (float*)d_out;

    // Identify inputs by element count; fall back to positional order.
    const float *x = 0, *adj = 0, *Wz = 0, *Wr = 0, *Wh = 0;
    const float *bz = 0, *br = 0, *bh = 0, *fcw = 0, *fcb = 0;
    for (int i = 0; i < n_in; i++) {
        const int s = in_sizes[i];
        const float* p = (const float*)d_in[i];
        if      (s == Nn * Tt * Dd) x = p;
        else if (s == Nn * Nn)      adj = p;
        else if (s == DH * Hh)      { if (!Wz) Wz = p; else if (!Wr) Wr = p; else Wh = p; }
        else if (s == Hh)           { if (!bz) bz = p; else if (!br) br = p; else bh = p; }
        else if (s == Hh * Ee)      fcw = p;
        else if (s == Ee)           fcb = p;
    }
    if ((!x || !adj || !Wz || !Wr || !Wh || !bz || !br || !bh || !fcw || !fcb)
        && n_in >= 10) {
        x   = (const float*)d_in[0];
        adj = (const float*)d_in[1];
        Wz  = (const float*)d_in[2];  bz = (const float*)d_in[3];
        Wr  = (const float*)d_in[4];  br = (const float*)d_in[5];
        Wh  = (const float*)d_in[6];  bh = (const float*)d_in[7];
        fcw = (const float*)d_in[8];  fcb = (const float*)d_in[9];
    }

    // ---- fold all three W@adj in one launch (240 CTAs)
    fold_k<<<dim3(8, 10, 3), 256>>>(Wz, Wr, Wh, adj);

    // ---- time-parallel x-path precompute (full machine)
    pre_k<0><<<dim3(16, 256), 256>>>(x, bz, br);
    pre_k<1><<<dim3(8, 256), 256>>>(x, bh, 0);

    // ---- t = 0 (h0 = 0: GEMMs degenerate to elementwise)
    step0_k<<<(Nn * Hh) / 256, 256>>>();
    fc_k<<<128, 256>>>(fcw, fcb, out, 0);

    // ---- recurrent loop (R13 structure, new fc)
    for (int t = 1; t < Tt; t++) {
        gates_k<<<dim3(16, 8), 256>>>(t);    // z and r*h   (128 CTAs)
        cand_k<<<dim3(8, 16), 256>>>(t);     // h update    (128 CTAs)
        fc_k<<<128, 256>>>(fcw, fcb, out, t);
    }
}